// round 2
// baseline (speedup 1.0000x reference)
#include <cuda_runtime.h>
#include <cuda_bf16.h>

#define CCONST 7.1998226
#define RPB 16        // rows per block
#define THREADS 256

// per-block fp64 partials: B * (N/RPB) = 16 * 128 = 2048 used
__device__ double g_part[8192];

__global__ __launch_bounds__(THREADS)
void coulomb_rows(const float* __restrict__ dij,
                  const float* __restrict__ q,
                  int N) {
    const int b   = blockIdx.y;
    const int rg  = blockIdx.x;
    const int tid = threadIdx.x;

    const float* qb = q + (size_t)b * N;
    const float4* q4p = (const float4*)qb;
    const int n4 = N >> 2;

    double acc = 0.0;

    for (int r = 0; r < RPB; r++) {
        const int row = rg * RPB + r;
        const float4* drow = (const float4*)(dij + ((size_t)b * N + row) * (size_t)N);

        float local = 0.0f;
        for (int c = tid; c < n4; c += THREADS) {
            float4 d4 = drow[c];
            float4 q4 = __ldg(q4p + c);
            local += q4.x / d4.x;
            local += q4.y / d4.y;
            local += q4.z / d4.z;
            local += q4.w / d4.w;
        }
        // promote to fp64 once per row
        acc += (double)__ldg(qb + row) * (double)local;
    }

    // warp reduce (fp64)
    #pragma unroll
    for (int off = 16; off; off >>= 1)
        acc += __shfl_down_sync(0xffffffffu, acc, off);

    __shared__ double sm[THREADS / 32];
    if ((tid & 31) == 0) sm[tid >> 5] = acc;
    __syncthreads();

    if (tid < 32) {
        double v = (tid < THREADS / 32) ? sm[tid] : 0.0;
        #pragma unroll
        for (int off = 4; off; off >>= 1)
            v += __shfl_down_sync(0xffffffffu, v, off);
        if (tid == 0)
            g_part[(size_t)b * gridDim.x + rg] = v;
    }
}

__global__ void coulomb_reduce(float* __restrict__ out, int per_b) {
    const int b   = blockIdx.x;
    const int tid = threadIdx.x;

    double v = 0.0;
    for (int i = tid; i < per_b; i += blockDim.x)
        v += g_part[(size_t)b * per_b + i];

    #pragma unroll
    for (int off = 16; off; off >>= 1)
        v += __shfl_down_sync(0xffffffffu, v, off);

    __shared__ double sm[32];
    if ((tid & 31) == 0) sm[tid >> 5] = v;
    __syncthreads();

    if (tid < 32) {
        const int nw = blockDim.x >> 5;
        double t = (tid < nw) ? sm[tid] : 0.0;
        #pragma unroll
        for (int off = 16; off; off >>= 1)
            t += __shfl_down_sync(0xffffffffu, t, off);
        if (tid == 0)
            out[b] = (float)(CCONST * t);   // output dtype: float32
    }
}

extern "C" void kernel_launch(void* const* d_in, const int* in_sizes, int n_in,
                              void* d_out, int out_size) {
    // Identify inputs by element count: the largest input is d_ij [B,N,N],
    // the other is q [B,N]. B comes from out_size.
    int di = 0;
    for (int i = 1; i < n_in; i++)
        if (in_sizes[i] > in_sizes[di]) di = i;

    const float* dij = (const float*)d_in[di];

    // q: the input (other than dij) whose size, divided by B, squares to dij's size
    const long long B = (out_size > 0) ? out_size : 16;
    int qi = (di == 0 && n_in > 1) ? 1 : 0;
    for (int i = 0; i < n_in; i++) {
        if (i == di) continue;
        long long nq = in_sizes[i];
        long long Nc = nq / B;
        if (Nc > 0 && B * Nc * Nc == (long long)in_sizes[di]) { qi = i; break; }
    }
    const float* q = (const float*)d_in[qi];

    const long long nq = in_sizes[qi];
    const int N = (int)(nq / B);                 // 2048
    const int row_groups = N / RPB;              // 128

    dim3 grid(row_groups, (unsigned)B);
    coulomb_rows<<<grid, THREADS>>>(dij, q, N);
    coulomb_reduce<<<(unsigned)B, 128>>>((float*)d_out, row_groups);
}

// round 3
// speedup vs baseline: 1.3235x; 1.3235x over previous
#include <cuda_runtime.h>
#include <cuda_bf16.h>

#define CCONST 7.1998226
#define RPB 16        // rows per block
#define THREADS 256

// per-block fp64 partials: B * (N/RPB) = 16 * 128 = 2048 used
__device__ double g_part[8192];

__global__ __launch_bounds__(THREADS)
void coulomb_rows(const float* __restrict__ dij,
                  const float* __restrict__ q,
                  int N) {
    const int b   = blockIdx.y;
    const int rg  = blockIdx.x;
    const int tid = threadIdx.x;

    const float* qb = q + (size_t)b * N;

    // fixed column ownership: 8 contiguous columns per thread, q_j in registers
    const int j0 = tid * 8;
    const float4 qa = __ldg((const float4*)(qb + j0));
    const float4 qc = __ldg((const float4*)(qb + j0 + 4));

    const int row0 = rg * RPB;
    const float* base = dij + ((size_t)b * N + row0) * (size_t)N + j0;

    double acc = 0.0;

#pragma unroll 4
    for (int r = 0; r < RPB; r++) {
        const float4* p = (const float4*)(base + (size_t)r * N);
        float4 da = p[0];
        float4 dc = p[1];

        // fast approximate division: MUFU.RCP + FMUL each
        float local;
        local  = __fdividef(qa.x, da.x);
        local += __fdividef(qa.y, da.y);
        local += __fdividef(qa.z, da.z);
        local += __fdividef(qa.w, da.w);
        local += __fdividef(qc.x, dc.x);
        local += __fdividef(qc.y, dc.y);
        local += __fdividef(qc.z, dc.z);
        local += __fdividef(qc.w, dc.w);

        // promote once per row: acc += q_i * rowPartial (fp64)
        acc = fma((double)__ldg(qb + row0 + r), (double)local, acc);
    }

    // warp reduce (fp64)
    #pragma unroll
    for (int off = 16; off; off >>= 1)
        acc += __shfl_down_sync(0xffffffffu, acc, off);

    __shared__ double sm[THREADS / 32];
    if ((tid & 31) == 0) sm[tid >> 5] = acc;
    __syncthreads();

    if (tid < 32) {
        double v = (tid < THREADS / 32) ? sm[tid] : 0.0;
        #pragma unroll
        for (int off = 4; off; off >>= 1)
            v += __shfl_down_sync(0xffffffffu, v, off);
        if (tid == 0)
            g_part[(size_t)b * gridDim.x + rg] = v;
    }
}

__global__ void coulomb_reduce(float* __restrict__ out, int per_b) {
    const int b   = blockIdx.x;
    const int tid = threadIdx.x;

    double v = 0.0;
    for (int i = tid; i < per_b; i += blockDim.x)
        v += g_part[(size_t)b * per_b + i];

    #pragma unroll
    for (int off = 16; off; off >>= 1)
        v += __shfl_down_sync(0xffffffffu, v, off);

    __shared__ double sm[32];
    if ((tid & 31) == 0) sm[tid >> 5] = v;
    __syncthreads();

    if (tid < 32) {
        const int nw = blockDim.x >> 5;
        double t = (tid < nw) ? sm[tid] : 0.0;
        #pragma unroll
        for (int off = 16; off; off >>= 1)
            t += __shfl_down_sync(0xffffffffu, t, off);
        if (tid == 0)
            out[b] = (float)(CCONST * t);
    }
}

extern "C" void kernel_launch(void* const* d_in, const int* in_sizes, int n_in,
                              void* d_out, int out_size) {
    // Identify inputs by element count: largest = d_ij [B,N,N]; q = [B,N].
    int di = 0;
    for (int i = 1; i < n_in; i++)
        if (in_sizes[i] > in_sizes[di]) di = i;

    const float* dij = (const float*)d_in[di];

    const long long B = (out_size > 0) ? out_size : 16;
    int qi = (di == 0 && n_in > 1) ? 1 : 0;
    for (int i = 0; i < n_in; i++) {
        if (i == di) continue;
        long long nq = in_sizes[i];
        long long Nc = nq / B;
        if (Nc > 0 && B * Nc * Nc == (long long)in_sizes[di]) { qi = i; break; }
    }
    const float* q = (const float*)d_in[qi];

    const int N = (int)((long long)in_sizes[qi] / B);   // 2048
    const int row_groups = N / RPB;                     // 128

    dim3 grid(row_groups, (unsigned)B);
    coulomb_rows<<<grid, THREADS>>>(dij, q, N);
    coulomb_reduce<<<(unsigned)B, 128>>>((float*)d_out, row_groups);
}

// round 4
// speedup vs baseline: 1.6533x; 1.2492x over previous
#include <cuda_runtime.h>
#include <cuda_bf16.h>

#define CCONST 7.1998226
#define RPB 16        // rows per block
#define THREADS 256

// per-block fp64 partials: B * (N/RPB) = 16 * 128 = 2048 used
__device__ double g_part[8192];

__global__ __launch_bounds__(THREADS)
void coulomb_rows(const float* __restrict__ dij,
                  const float* __restrict__ q,
                  int N) {
    const int b   = blockIdx.y;
    const int rg  = blockIdx.x;
    const int tid = threadIdx.x;

    const float* qb = q + (size_t)b * N;

    // fixed column ownership: 8 contiguous columns per thread, q_j in registers
    const int j0 = tid * 8;
    const float4 qa = __ldg((const float4*)(qb + j0));
    const float4 qc = __ldg((const float4*)(qb + j0 + 4));

    const int row0 = rg * RPB;
    const float* base = dij + ((size_t)b * N + row0) * (size_t)N + j0;

    // q_i for the 16 rows this block owns: preload into registers
    float qi[RPB];
#pragma unroll
    for (int r = 0; r < RPB; r++) qi[r] = __ldg(qb + row0 + r);

    // two independent f32 accumulators — no fp64 in the hot loop
    float acc0 = 0.0f, acc1 = 0.0f;

#pragma unroll
    for (int r = 0; r < RPB; r += 2) {
        const float4* p0 = (const float4*)(base + (size_t)r * N);
        const float4* p1 = (const float4*)(base + (size_t)(r + 1) * N);
        float4 da0 = p0[0], dc0 = p0[1];
        float4 da1 = p1[0], dc1 = p1[1];

        float l0;
        l0  = __fdividef(qa.x, da0.x);
        l0 += __fdividef(qa.y, da0.y);
        l0 += __fdividef(qa.z, da0.z);
        l0 += __fdividef(qa.w, da0.w);
        l0 += __fdividef(qc.x, dc0.x);
        l0 += __fdividef(qc.y, dc0.y);
        l0 += __fdividef(qc.z, dc0.z);
        l0 += __fdividef(qc.w, dc0.w);
        acc0 = fmaf(qi[r], l0, acc0);

        float l1;
        l1  = __fdividef(qa.x, da1.x);
        l1 += __fdividef(qa.y, da1.y);
        l1 += __fdividef(qa.z, da1.z);
        l1 += __fdividef(qa.w, da1.w);
        l1 += __fdividef(qc.x, dc1.x);
        l1 += __fdividef(qc.y, dc1.y);
        l1 += __fdividef(qc.z, dc1.z);
        l1 += __fdividef(qc.w, dc1.w);
        acc1 = fmaf(qi[r + 1], l1, acc1);
    }

    // single promote to fp64 per thread, then warp reduce
    double acc = (double)acc0 + (double)acc1;

    #pragma unroll
    for (int off = 16; off; off >>= 1)
        acc += __shfl_down_sync(0xffffffffu, acc, off);

    __shared__ double sm[THREADS / 32];
    if ((tid & 31) == 0) sm[tid >> 5] = acc;
    __syncthreads();

    if (tid < 32) {
        double v = (tid < THREADS / 32) ? sm[tid] : 0.0;
        #pragma unroll
        for (int off = 4; off; off >>= 1)
            v += __shfl_down_sync(0xffffffffu, v, off);
        if (tid == 0)
            g_part[(size_t)b * gridDim.x + rg] = v;
    }
}

__global__ void coulomb_reduce(float* __restrict__ out, int per_b) {
    const int b   = blockIdx.x;
    const int tid = threadIdx.x;

    double v = 0.0;
    for (int i = tid; i < per_b; i += blockDim.x)
        v += g_part[(size_t)b * per_b + i];

    #pragma unroll
    for (int off = 16; off; off >>= 1)
        v += __shfl_down_sync(0xffffffffu, v, off);

    __shared__ double sm[32];
    if ((tid & 31) == 0) sm[tid >> 5] = v;
    __syncthreads();

    if (tid < 32) {
        const int nw = blockDim.x >> 5;
        double t = (tid < nw) ? sm[tid] : 0.0;
        #pragma unroll
        for (int off = 16; off; off >>= 1)
            t += __shfl_down_sync(0xffffffffu, t, off);
        if (tid == 0)
            out[b] = (float)(CCONST * t);
    }
}

extern "C" void kernel_launch(void* const* d_in, const int* in_sizes, int n_in,
                              void* d_out, int out_size) {
    // Identify inputs by element count: largest = d_ij [B,N,N]; q = [B,N].
    int di = 0;
    for (int i = 1; i < n_in; i++)
        if (in_sizes[i] > in_sizes[di]) di = i;

    const float* dij = (const float*)d_in[di];

    const long long B = (out_size > 0) ? out_size : 16;
    int qi = (di == 0 && n_in > 1) ? 1 : 0;
    for (int i = 0; i < n_in; i++) {
        if (i == di) continue;
        long long nq = in_sizes[i];
        long long Nc = nq / B;
        if (Nc > 0 && B * Nc * Nc == (long long)in_sizes[di]) { qi = i; break; }
    }
    const float* q = (const float*)d_in[qi];

    const int N = (int)((long long)in_sizes[qi] / B);   // 2048
    const int row_groups = N / RPB;                     // 128

    dim3 grid(row_groups, (unsigned)B);
    coulomb_rows<<<grid, THREADS>>>(dij, q, N);
    coulomb_reduce<<<(unsigned)B, 128>>>((float*)d_out, row_groups);
}